// round 10
// baseline (speedup 1.0000x reference)
#include <cuda_runtime.h>
#include <cuda_bf16.h>

// ---------------- problem constants -----------------------------------------
#define N_TOK 8192
#define H_DIM 1024
#define F_DIM 4096
#define E_NUM 8
#define K_CAP 1280   // int(8192 * 1.25 / 8)

// ---------------- scratch (static device globals, no allocation) ------------
__device__ unsigned long long g_keys[E_NUM * N_TOK];
__device__ unsigned long long g_part[E_NUM * 2 * K_CAP];
__device__ int   g_indices[E_NUM * K_CAP];
__device__ int   g_slot[N_TOK * E_NUM];
__device__ float g_h [(size_t)E_NUM * K_CAP * F_DIM];       // fp32 intermediate
__device__ float g_eo[(size_t)2 * E_NUM * K_CAP * H_DIM];   // 2 split-K planes

#define EOP ((size_t)E_NUM * K_CAP * H_DIM)

// ---------------- helpers -----------------------------------------------------
__device__ __forceinline__ unsigned smem_u32(const void* p) {
    unsigned a;
    asm("{ .reg .u64 t; cvta.to.shared.u64 t, %1; cvt.u32.u64 %0, t; }" : "=r"(a) : "l"(p));
    return a;
}
__device__ __forceinline__ void ldsm4(unsigned& r0, unsigned& r1, unsigned& r2,
                                      unsigned& r3, unsigned addr) {
    asm volatile("ldmatrix.sync.aligned.m8n8.x4.shared.b16 {%0,%1,%2,%3}, [%4];"
                 : "=r"(r0), "=r"(r1), "=r"(r2), "=r"(r3) : "r"(addr));
}
__device__ __forceinline__ void ldsm4t(unsigned& r0, unsigned& r1, unsigned& r2,
                                       unsigned& r3, unsigned addr) {
    asm volatile("ldmatrix.sync.aligned.m8n8.x4.trans.shared.b16 {%0,%1,%2,%3}, [%4];"
                 : "=r"(r0), "=r"(r1), "=r"(r2), "=r"(r3) : "r"(addr));
}
__device__ __forceinline__ void mma16816(float* c, const unsigned* a, const unsigned* b) {
    asm volatile("mma.sync.aligned.m16n8k16.row.col.f32.bf16.bf16.f32 "
                 "{%0,%1,%2,%3}, {%4,%5,%6,%7}, {%8,%9}, {%0,%1,%2,%3};"
                 : "+f"(c[0]), "+f"(c[1]), "+f"(c[2]), "+f"(c[3])
                 : "r"(a[0]), "r"(a[1]), "r"(a[2]), "r"(a[3]), "r"(b[0]), "r"(b[1]));
}
// split float4 into packed hi (2x u32) and lo (2x u32), pairwise cvt
__device__ __forceinline__ void cvt_split4(float4 v, uint2& hi, uint2& lo) {
    __nv_bfloat162 h01 = __float22bfloat162_rn(make_float2(v.x, v.y));
    __nv_bfloat162 h23 = __float22bfloat162_rn(make_float2(v.z, v.w));
    float2 f01 = __bfloat1622float2(h01);
    float2 f23 = __bfloat1622float2(h23);
    __nv_bfloat162 l01 = __float22bfloat162_rn(make_float2(v.x - f01.x, v.y - f01.y));
    __nv_bfloat162 l23 = __float22bfloat162_rn(make_float2(v.z - f23.x, v.w - f23.y));
    hi.x = *reinterpret_cast<unsigned*>(&h01);
    hi.y = *reinterpret_cast<unsigned*>(&h23);
    lo.x = *reinterpret_cast<unsigned*>(&l01);
    lo.y = *reinterpret_cast<unsigned*>(&l23);
}
__device__ __forceinline__ float silu_f(float v) { return v / (1.0f + expf(-v)); }

// ---------------- gating: fp64-accurate logits -> sortable 64-bit keys ------
__global__ void gate_kernel(const float* __restrict__ x,
                            const float* __restrict__ gw) {
    int t = blockIdx.x;
    int tid = threadIdx.x;
    double acc[E_NUM];
#pragma unroll
    for (int e = 0; e < E_NUM; ++e) acc[e] = 0.0;
    const float* xr = x + (size_t)t * H_DIM;
    for (int h = tid; h < H_DIM; h += 256) {
        double xv = (double)xr[h];
        const float* g = gw + h * E_NUM;
#pragma unroll
        for (int e = 0; e < E_NUM; ++e) acc[e] += xv * (double)g[e];
    }
#pragma unroll
    for (int e = 0; e < E_NUM; ++e) {
#pragma unroll
        for (int off = 16; off > 0; off >>= 1)
            acc[e] += __shfl_down_sync(0xffffffffu, acc[e], off);
    }
    __shared__ double red[8][E_NUM];
    int warp = tid >> 5, lane = tid & 31;
    if (lane == 0) {
#pragma unroll
        for (int e = 0; e < E_NUM; ++e) red[warp][e] = acc[e];
    }
    __syncthreads();
    if (tid < E_NUM) {
        double s = 0.0;
        for (int w = 0; w < 8; ++w) s += red[w][tid];
        float lf = (float)s;
        unsigned u = __float_as_uint(lf);
        u = (u & 0x80000000u) ? ~u : (u | 0x80000000u);
        unsigned long long key =
            ((unsigned long long)u << 13) | (unsigned)(8191 - t);
        g_keys[tid * N_TOK + t] = key;
        g_slot[t * E_NUM + tid] = -1;
    }
}

// ---------------- per-expert half-sort (bitonic, 4096 elems) ----------------
__global__ void sort_half_kernel() {
    __shared__ unsigned long long s[4096];
    int e = blockIdx.y, half = blockIdx.x;
    const unsigned long long* keys = g_keys + e * N_TOK + half * 4096;
    for (int i = threadIdx.x; i < 4096; i += 1024) s[i] = ~keys[i];
    __syncthreads();
    for (int k = 2; k <= 4096; k <<= 1) {
        for (int j = k >> 1; j > 0; j >>= 1) {
            for (int base = 0; base < 4096; base += 1024) {
                int i = base + threadIdx.x;
                int l = i ^ j;
                if (l > i) {
                    unsigned long long a = s[i], b = s[l];
                    bool up = ((i & k) == 0);
                    if (up ? (a > b) : (a < b)) { s[i] = b; s[l] = a; }
                }
            }
            __syncthreads();
        }
    }
    for (int i = threadIdx.x; i < K_CAP; i += 1024)
        g_part[(e * 2 + half) * K_CAP + i] = ~s[i];
}

// ---------------- merge the two sorted half-lists by rank -------------------
__global__ void merge_topk_kernel() {
    int e = blockIdx.x;
    const unsigned long long* A = g_part + (size_t)(e * 2 + 0) * K_CAP;
    const unsigned long long* B = g_part + (size_t)(e * 2 + 1) * K_CAP;
    for (int idx = threadIdx.x; idx < 2 * K_CAP; idx += blockDim.x) {
        bool inA = idx < K_CAP;
        const unsigned long long* other = inA ? B : A;
        int i = inA ? idx : idx - K_CAP;
        unsigned long long v = (inA ? A : B)[i];
        int lo = 0, hi = K_CAP;
        while (lo < hi) {
            int mid = (lo + hi) >> 1;
            if (other[mid] > v) lo = mid + 1; else hi = mid;
        }
        int rank = i + lo;
        if (rank < K_CAP) {
            int t = 8191 - (int)(v & 0x1FFFull);
            g_indices[e * K_CAP + rank] = t;
            g_slot[t * E_NUM + e] = rank;
        }
    }
}

// ---------------- HMMA GEMM: 128x128 tile, BK=16, double-buffered -----------
// Per buffer (24 KB): Ah[128x64B] swz u^(m&3) | Al | Bh[16x256B] swz u^(k&7) | Bl
// 2 buffers = 48 KB static. 4 warps, warp tile 64x64, 3-term bf16 split.
template<bool FIRST, int KSPLIT>
__global__ __launch_bounds__(128, 2)
void moe_gemm_kernel(const float* __restrict__ x,
                     const float* __restrict__ w) {
    constexpr int KTOT = FIRST ? H_DIM : F_DIM;
    constexpr int KLOC = KTOT / KSPLIT;
    constexpr int NEXP = FIRST ? F_DIM : H_DIM;
    constexpr int NCH  = KLOC / 16;
    constexpr unsigned AH = 0, AL = 8192, BH = 16384, BL = 20480;

    __shared__ __align__(1024) unsigned char buf[2][24576];   // 48 KB exactly

    const int tid  = threadIdx.x;
    const int wid  = tid >> 5, lane = tid & 31;
    const int e    = blockIdx.z / KSPLIT;
    const int kh   = blockIdx.z % KSPLIT;
    const int m0   = blockIdx.y * 128, n0 = blockIdx.x * 128;
    const int wm   = (wid >> 1) * 64;
    const int wn   = (wid & 1) * 64;

    const unsigned sb0 = smem_u32(buf[0]);
    const unsigned sb1 = smem_u32(buf[1]);

    // ---- token ids via smem overlay on buf[0] (GEMM1 only) ----
    int* stok = (int*)buf[0];
    if (FIRST) stok[tid] = g_indices[e * K_CAP + m0 + tid];
    __syncthreads();

    // ---- staging maps ----
    const int af     = tid & 3;    // A: float4 unit within 16-k row
    const int arow_g = tid >> 2;   // A: row = j*32 + arow_g  (j = 0..3)
    const int bc     = tid & 31;   // B: col block (4 floats)
    const int brow_g = tid >> 5;   // B: row = brow_g*4 + j   (j = 0..3)

    const float* abase[4];
#pragma unroll
    for (int j = 0; j < 4; ++j) {
        int row = j * 32 + arow_g;
        if (FIRST)
            abase[j] = x + (size_t)stok[row] * H_DIM + kh * KLOC + af * 4;
        else
            abase[j] = g_h + ((size_t)e * K_CAP + m0 + row) * F_DIM + kh * KLOC + af * 4;
    }
    const float* bbase = w + (size_t)e * KTOT * NEXP
                         + (size_t)(kh * KLOC + brow_g * 4) * NEXP + n0 + bc * 4;
    __syncthreads();   // all stok reads done before buf[0] is overwritten

    float acc[4][8][4];
#pragma unroll
    for (int mt = 0; mt < 4; ++mt)
#pragma unroll
        for (int nt = 0; nt < 8; ++nt)
#pragma unroll
            for (int q = 0; q < 4; ++q) acc[mt][nt][q] = 0.0f;

    // precomputed store addresses (buffer-relative, loop-invariant)
    unsigned a_st[4], b_st[4];
#pragma unroll
    for (int j = 0; j < 4; ++j) {
        unsigned srow = (unsigned)(j * 32 + arow_g);
        a_st[j] = srow * 64u
                + ((((unsigned)af >> 1) ^ (srow & 3u)) * 16u) + (af & 1) * 8u;
        unsigned brow = (unsigned)(brow_g * 4 + j);
        b_st[j] = brow * 256u
                + ((((unsigned)bc >> 1) ^ (brow & 7u)) * 16u) + (bc & 1) * 8u;
    }

    auto stage = [&](int kt, unsigned base) {
#pragma unroll
        for (int j = 0; j < 4; ++j) {
            float4 v = *(const float4*)(abase[j] + kt * 16);
            uint2 hi, lo;
            cvt_split4(v, hi, lo);
            *(uint2*)(buf[0] + (base - sb0) + AH + a_st[j]) = hi;
            *(uint2*)(buf[0] + (base - sb0) + AL + a_st[j]) = lo;
        }
#pragma unroll
        for (int j = 0; j < 4; ++j) {
            float4 v = *(const float4*)(bbase + (size_t)(kt * 16 + j) * NEXP);
            uint2 hi, lo;
            cvt_split4(v, hi, lo);
            *(uint2*)(buf[0] + (base - sb0) + BH + b_st[j]) = hi;
            *(uint2*)(buf[0] + (base - sb0) + BL + b_st[j]) = lo;
        }
    };

    auto compute = [&](unsigned base) {
        unsigned ah[4][4], al[4][4];
#pragma unroll
        for (int mt = 0; mt < 4; ++mt) {
            unsigned row = (unsigned)(wm + mt * 16 + (lane & 15));
            unsigned unit = (unsigned)(lane >> 4);
            unsigned off = row * 64u + ((unit ^ (row & 3u)) * 16u);
            ldsm4(ah[mt][0], ah[mt][1], ah[mt][2], ah[mt][3], base + AH + off);
            ldsm4(al[mt][0], al[mt][1], al[mt][2], al[mt][3], base + AL + off);
        }
        unsigned bh[8][2], bl[8][2];
#pragma unroll
        for (int p = 0; p < 4; ++p) {
            int g = lane >> 3;
            unsigned krow = (unsigned)((g & 1) * 8 + (lane & 7));
            unsigned unit = (unsigned)((wn >> 3) + 2 * p + (g >> 1));
            unsigned off = krow * 256u + ((unit ^ (krow & 7u)) * 16u);
            unsigned r0, r1, r2, r3;
            ldsm4t(r0, r1, r2, r3, base + BH + off);
            bh[2 * p][0] = r0;     bh[2 * p][1] = r1;
            bh[2 * p + 1][0] = r2; bh[2 * p + 1][1] = r3;
            ldsm4t(r0, r1, r2, r3, base + BL + off);
            bl[2 * p][0] = r0;     bl[2 * p][1] = r1;
            bl[2 * p + 1][0] = r2; bl[2 * p + 1][1] = r3;
        }
#pragma unroll
        for (int mt = 0; mt < 4; ++mt)
#pragma unroll
            for (int nt = 0; nt < 8; ++nt) {
                mma16816(acc[mt][nt], ah[mt], bh[nt]);
                mma16816(acc[mt][nt], al[mt], bh[nt]);
                mma16816(acc[mt][nt], ah[mt], bl[nt]);
            }
    };

    // ---- double-buffered main loop: stage(next) overlaps compute(cur) ----
    stage(0, sb0);
    __syncthreads();
    for (int kt = 0; kt < NCH; ++kt) {
        unsigned cur = (kt & 1) ? sb1 : sb0;
        unsigned nxt = (kt & 1) ? sb0 : sb1;
        if (kt + 1 < NCH) stage(kt + 1, nxt);
        compute(cur);
        __syncthreads();
    }

    // ---- epilogue ----
#pragma unroll
    for (int mt = 0; mt < 4; ++mt) {
#pragma unroll
        for (int nt = 0; nt < 8; ++nt) {
            int row0 = m0 + wm + mt * 16 + (lane >> 2);
            int cc   = n0 + wn + nt * 8 + 2 * (lane & 3);
#pragma unroll
            for (int hrow = 0; hrow < 2; ++hrow) {
                float v0 = acc[mt][nt][2 * hrow + 0];
                float v1 = acc[mt][nt][2 * hrow + 1];
                if (FIRST) {
                    size_t g0 = ((size_t)e * K_CAP + row0 + 8 * hrow) * (size_t)F_DIM + cc;
                    float2 s;
                    s.x = silu_f(v0);
                    s.y = silu_f(v1);
                    *(float2*)(g_h + g0) = s;
                } else {
                    size_t g0 = kh * EOP
                              + ((size_t)e * K_CAP + row0 + 8 * hrow) * (size_t)H_DIM + cc;
                    float2 s;
                    s.x = v0;
                    s.y = v1;
                    *(float2*)(g_eo + g0) = s;
                }
            }
        }
    }
}

// ---------------- deterministic scatter (sums both split-K planes) ----------
__global__ void scatter_kernel(float* __restrict__ out) {
    int t = blockIdx.x, tid = threadIdx.x;
    __shared__ int ssl[E_NUM];
    if (tid < E_NUM) ssl[tid] = g_slot[t * E_NUM + tid];
    __syncthreads();
    int j = tid * 4;
    float4 sum = make_float4(0.f, 0.f, 0.f, 0.f);
#pragma unroll
    for (int e = 0; e < E_NUM; ++e) {
        int sl = ssl[e];
        if (sl >= 0) {
            size_t base = ((size_t)e * K_CAP + sl) * H_DIM + j;
            float4 v0 = *(const float4*)(g_eo + base);
            float4 v1 = *(const float4*)(g_eo + EOP + base);
            sum.x += v0.x + v1.x; sum.y += v0.y + v1.y;
            sum.z += v0.z + v1.z; sum.w += v0.w + v1.w;
        }
    }
    *(float4*)(out + (size_t)t * H_DIM + j) = sum;
}

// ---------------- launch ----------------------------------------------------
extern "C" void kernel_launch(void* const* d_in, const int* in_sizes, int n_in,
                              void* d_out, int out_size) {
    const float* x  = (const float*)d_in[0];   // [4,2048,1024]
    const float* gw = (const float*)d_in[1];   // [1024,8]
    const float* w1 = (const float*)d_in[2];   // [8,1024,4096]
    const float* w2 = (const float*)d_in[3];   // [8,4096,1024]
    float* out = (float*)d_out;
    (void)in_sizes; (void)n_in;

    // loss scalar = 0 exactly (expert_load == k for all experts)
    cudaMemsetAsync(d_out, 0, (size_t)out_size * sizeof(float), 0);

    gate_kernel<<<N_TOK, 256>>>(x, gw);
    sort_half_kernel<<<dim3(2, E_NUM), 1024>>>();
    merge_topk_kernel<<<E_NUM, 256>>>();

    moe_gemm_kernel<true, 1><<<dim3(F_DIM / 128, K_CAP / 128, E_NUM), 128>>>(x, w1);
    moe_gemm_kernel<false, 2><<<dim3(H_DIM / 128, K_CAP / 128, E_NUM * 2), 128>>>(nullptr, w2);

    scatter_kernel<<<N_TOK, 256>>>(out);
}

// round 11
// speedup vs baseline: 1.1872x; 1.1872x over previous
#include <cuda_runtime.h>
#include <cuda_bf16.h>

// ---------------- problem constants -----------------------------------------
#define N_TOK 8192
#define H_DIM 1024
#define F_DIM 4096
#define E_NUM 8
#define K_CAP 1280   // int(8192 * 1.25 / 8)

// ---------------- scratch (static device globals, no allocation) ------------
__device__ unsigned long long g_keys[E_NUM * N_TOK];
__device__ unsigned long long g_part[E_NUM * 2 * K_CAP];
__device__ int   g_indices[E_NUM * K_CAP];
__device__ int   g_slot[N_TOK * E_NUM];
__device__ float g_h [(size_t)E_NUM * K_CAP * F_DIM];       // fp32 intermediate
__device__ float g_eo[(size_t)2 * E_NUM * K_CAP * H_DIM];   // 2 split-K planes

#define EOP ((size_t)E_NUM * K_CAP * H_DIM)

// ---------------- helpers -----------------------------------------------------
__device__ __forceinline__ unsigned smem_u32(const void* p) {
    unsigned a;
    asm("{ .reg .u64 t; cvta.to.shared.u64 t, %1; cvt.u32.u64 %0, t; }" : "=r"(a) : "l"(p));
    return a;
}
__device__ __forceinline__ void ldsm4(unsigned& r0, unsigned& r1, unsigned& r2,
                                      unsigned& r3, unsigned addr) {
    asm volatile("ldmatrix.sync.aligned.m8n8.x4.shared.b16 {%0,%1,%2,%3}, [%4];"
                 : "=r"(r0), "=r"(r1), "=r"(r2), "=r"(r3) : "r"(addr));
}
__device__ __forceinline__ void ldsm4t(unsigned& r0, unsigned& r1, unsigned& r2,
                                       unsigned& r3, unsigned addr) {
    asm volatile("ldmatrix.sync.aligned.m8n8.x4.trans.shared.b16 {%0,%1,%2,%3}, [%4];"
                 : "=r"(r0), "=r"(r1), "=r"(r2), "=r"(r3) : "r"(addr));
}
__device__ __forceinline__ void mma16816(float* c, const unsigned* a, const unsigned* b) {
    asm volatile("mma.sync.aligned.m16n8k16.row.col.f32.bf16.bf16.f32 "
                 "{%0,%1,%2,%3}, {%4,%5,%6,%7}, {%8,%9}, {%0,%1,%2,%3};"
                 : "+f"(c[0]), "+f"(c[1]), "+f"(c[2]), "+f"(c[3])
                 : "r"(a[0]), "r"(a[1]), "r"(a[2]), "r"(a[3]), "r"(b[0]), "r"(b[1]));
}
// split float4 into packed hi (2x u32) and lo (2x u32), pairwise cvt
__device__ __forceinline__ void cvt_split4(float4 v, uint2& hi, uint2& lo) {
    __nv_bfloat162 h01 = __float22bfloat162_rn(make_float2(v.x, v.y));
    __nv_bfloat162 h23 = __float22bfloat162_rn(make_float2(v.z, v.w));
    float2 f01 = __bfloat1622float2(h01);
    float2 f23 = __bfloat1622float2(h23);
    __nv_bfloat162 l01 = __float22bfloat162_rn(make_float2(v.x - f01.x, v.y - f01.y));
    __nv_bfloat162 l23 = __float22bfloat162_rn(make_float2(v.z - f23.x, v.w - f23.y));
    hi.x = *reinterpret_cast<unsigned*>(&h01);
    hi.y = *reinterpret_cast<unsigned*>(&h23);
    lo.x = *reinterpret_cast<unsigned*>(&l01);
    lo.y = *reinterpret_cast<unsigned*>(&l23);
}
__device__ __forceinline__ float silu_f(float v) { return v / (1.0f + expf(-v)); }

// ---------------- gating: fp64-accurate logits -> sortable 64-bit keys ------
__global__ void gate_kernel(const float* __restrict__ x,
                            const float* __restrict__ gw) {
    int t = blockIdx.x;
    int tid = threadIdx.x;
    double acc[E_NUM];
#pragma unroll
    for (int e = 0; e < E_NUM; ++e) acc[e] = 0.0;
    const float* xr = x + (size_t)t * H_DIM;
    for (int h = tid; h < H_DIM; h += 256) {
        double xv = (double)xr[h];
        const float* g = gw + h * E_NUM;
#pragma unroll
        for (int e = 0; e < E_NUM; ++e) acc[e] += xv * (double)g[e];
    }
#pragma unroll
    for (int e = 0; e < E_NUM; ++e) {
#pragma unroll
        for (int off = 16; off > 0; off >>= 1)
            acc[e] += __shfl_down_sync(0xffffffffu, acc[e], off);
    }
    __shared__ double red[8][E_NUM];
    int warp = tid >> 5, lane = tid & 31;
    if (lane == 0) {
#pragma unroll
        for (int e = 0; e < E_NUM; ++e) red[warp][e] = acc[e];
    }
    __syncthreads();
    if (tid < E_NUM) {
        double s = 0.0;
        for (int w = 0; w < 8; ++w) s += red[w][tid];
        float lf = (float)s;
        unsigned u = __float_as_uint(lf);
        u = (u & 0x80000000u) ? ~u : (u | 0x80000000u);
        unsigned long long key =
            ((unsigned long long)u << 13) | (unsigned)(8191 - t);
        g_keys[tid * N_TOK + t] = key;
        g_slot[t * E_NUM + tid] = -1;
    }
}

// ---------------- per-expert half-sort (bitonic, 4096 elems) ----------------
__global__ void sort_half_kernel() {
    __shared__ unsigned long long s[4096];
    int e = blockIdx.y, half = blockIdx.x;
    const unsigned long long* keys = g_keys + e * N_TOK + half * 4096;
    for (int i = threadIdx.x; i < 4096; i += 1024) s[i] = ~keys[i];
    __syncthreads();
    for (int k = 2; k <= 4096; k <<= 1) {
        for (int j = k >> 1; j > 0; j >>= 1) {
            for (int base = 0; base < 4096; base += 1024) {
                int i = base + threadIdx.x;
                int l = i ^ j;
                if (l > i) {
                    unsigned long long a = s[i], b = s[l];
                    bool up = ((i & k) == 0);
                    if (up ? (a > b) : (a < b)) { s[i] = b; s[l] = a; }
                }
            }
            __syncthreads();
        }
    }
    for (int i = threadIdx.x; i < K_CAP; i += 1024)
        g_part[(e * 2 + half) * K_CAP + i] = ~s[i];
}

// ---------------- merge the two sorted half-lists by rank -------------------
__global__ void merge_topk_kernel() {
    int e = blockIdx.x;
    const unsigned long long* A = g_part + (size_t)(e * 2 + 0) * K_CAP;
    const unsigned long long* B = g_part + (size_t)(e * 2 + 1) * K_CAP;
    for (int idx = threadIdx.x; idx < 2 * K_CAP; idx += blockDim.x) {
        bool inA = idx < K_CAP;
        const unsigned long long* other = inA ? B : A;
        int i = inA ? idx : idx - K_CAP;
        unsigned long long v = (inA ? A : B)[i];
        int lo = 0, hi = K_CAP;
        while (lo < hi) {
            int mid = (lo + hi) >> 1;
            if (other[mid] > v) lo = mid + 1; else hi = mid;
        }
        int rank = i + lo;
        if (rank < K_CAP) {
            int t = 8191 - (int)(v & 0x1FFFull);
            g_indices[e * K_CAP + rank] = t;
            g_slot[t * E_NUM + e] = rank;
        }
    }
}

// ---------------- HMMA GEMM: 128x128 tile, BK=16, reg-prefetch pipeline -----
// Per buffer (24 KB): Ah[128x64B] swz u^(m&3) | Al | Bh[16x256B] swz u^(k&7) | Bl
// Loop: STS(regs->buf[kt&1]) ; sync ; LDG(kt+1->regs) ; compute(buf[kt&1])
// LDG latency hides behind MMA; only CVT+STS is exposed.
template<bool FIRST, int KSPLIT>
__global__ __launch_bounds__(128, 2)
void moe_gemm_kernel(const float* __restrict__ x,
                     const float* __restrict__ w) {
    constexpr int KTOT = FIRST ? H_DIM : F_DIM;
    constexpr int KLOC = KTOT / KSPLIT;
    constexpr int NEXP = FIRST ? F_DIM : H_DIM;
    constexpr int NCH  = KLOC / 16;
    constexpr unsigned AH = 0, AL = 8192, BH = 16384, BL = 20480;

    __shared__ __align__(1024) unsigned char buf[2][24576];   // 48 KB exactly

    const int tid  = threadIdx.x;
    const int wid  = tid >> 5, lane = tid & 31;
    const int e    = blockIdx.z / KSPLIT;
    const int kh   = blockIdx.z % KSPLIT;
    const int m0   = blockIdx.y * 128, n0 = blockIdx.x * 128;
    const int wm   = (wid >> 1) * 64;
    const int wn   = (wid & 1) * 64;

    const unsigned sb0 = smem_u32(buf[0]);

    // ---- token ids via smem overlay on buf[0] (GEMM1 only) ----
    int* stok = (int*)buf[0];
    if (FIRST) stok[tid] = g_indices[e * K_CAP + m0 + tid];
    __syncthreads();

    // ---- staging maps ----
    const int af     = tid & 3;    // A: float4 unit within 16-k row
    const int arow_g = tid >> 2;   // A: row = j*32 + arow_g  (j = 0..3)
    const int bc     = tid & 31;   // B: col block (4 floats)
    const int brow_g = tid >> 5;   // B: row = brow_g*4 + j   (j = 0..3)

    const float* abase[4];
#pragma unroll
    for (int j = 0; j < 4; ++j) {
        int row = j * 32 + arow_g;
        if (FIRST)
            abase[j] = x + (size_t)stok[row] * H_DIM + kh * KLOC + af * 4;
        else
            abase[j] = g_h + ((size_t)e * K_CAP + m0 + row) * F_DIM + kh * KLOC + af * 4;
    }
    const float* bbase = w + (size_t)e * KTOT * NEXP
                         + (size_t)(kh * KLOC + brow_g * 4) * NEXP + n0 + bc * 4;
    __syncthreads();   // all stok reads done before buf[0] is overwritten

    float acc[4][8][4];
#pragma unroll
    for (int mt = 0; mt < 4; ++mt)
#pragma unroll
        for (int nt = 0; nt < 8; ++nt)
#pragma unroll
            for (int q = 0; q < 4; ++q) acc[mt][nt][q] = 0.0f;

    // precomputed store addresses (buffer-relative, loop-invariant)
    unsigned a_st[4], b_st[4];
#pragma unroll
    for (int j = 0; j < 4; ++j) {
        unsigned srow = (unsigned)(j * 32 + arow_g);
        a_st[j] = srow * 64u
                + ((((unsigned)af >> 1) ^ (srow & 3u)) * 16u) + (af & 1) * 8u;
        unsigned brow = (unsigned)(brow_g * 4 + j);
        b_st[j] = brow * 256u
                + ((((unsigned)bc >> 1) ^ (brow & 7u)) * 16u) + (bc & 1) * 8u;
    }

    // ---- pipeline pieces ----
    float4 pa[4], pb[4];   // prefetch registers (32 regs)

    auto ldg_chunk = [&](int kt) {
#pragma unroll
        for (int j = 0; j < 4; ++j)
            pa[j] = *(const float4*)(abase[j] + kt * 16);
#pragma unroll
        for (int j = 0; j < 4; ++j)
            pb[j] = *(const float4*)(bbase + (size_t)(kt * 16 + j) * NEXP);
    };

    auto sts_chunk = [&](int bi) {
        unsigned char* bp = buf[0] + (size_t)bi * 24576;
#pragma unroll
        for (int j = 0; j < 4; ++j) {
            uint2 hi, lo;
            cvt_split4(pa[j], hi, lo);
            *(uint2*)(bp + AH + a_st[j]) = hi;
            *(uint2*)(bp + AL + a_st[j]) = lo;
        }
#pragma unroll
        for (int j = 0; j < 4; ++j) {
            uint2 hi, lo;
            cvt_split4(pb[j], hi, lo);
            *(uint2*)(bp + BH + b_st[j]) = hi;
            *(uint2*)(bp + BL + b_st[j]) = lo;
        }
    };

    auto compute = [&](unsigned base) {
        unsigned ah[4][4], al[4][4];
#pragma unroll
        for (int mt = 0; mt < 4; ++mt) {
            unsigned row = (unsigned)(wm + mt * 16 + (lane & 15));
            unsigned unit = (unsigned)(lane >> 4);
            unsigned off = row * 64u + ((unit ^ (row & 3u)) * 16u);
            ldsm4(ah[mt][0], ah[mt][1], ah[mt][2], ah[mt][3], base + AH + off);
            ldsm4(al[mt][0], al[mt][1], al[mt][2], al[mt][3], base + AL + off);
        }
        unsigned bh[8][2], bl[8][2];
#pragma unroll
        for (int p = 0; p < 4; ++p) {
            int g = lane >> 3;
            unsigned krow = (unsigned)((g & 1) * 8 + (lane & 7));
            unsigned unit = (unsigned)((wn >> 3) + 2 * p + (g >> 1));
            unsigned off = krow * 256u + ((unit ^ (krow & 7u)) * 16u);
            unsigned r0, r1, r2, r3;
            ldsm4t(r0, r1, r2, r3, base + BH + off);
            bh[2 * p][0] = r0;     bh[2 * p][1] = r1;
            bh[2 * p + 1][0] = r2; bh[2 * p + 1][1] = r3;
            ldsm4t(r0, r1, r2, r3, base + BL + off);
            bl[2 * p][0] = r0;     bl[2 * p][1] = r1;
            bl[2 * p + 1][0] = r2; bl[2 * p + 1][1] = r3;
        }
#pragma unroll
        for (int mt = 0; mt < 4; ++mt)
#pragma unroll
            for (int nt = 0; nt < 8; ++nt) {
                mma16816(acc[mt][nt], ah[mt], bh[nt]);
                mma16816(acc[mt][nt], al[mt], bh[nt]);
                mma16816(acc[mt][nt], ah[mt], bl[nt]);
            }
    };

    // ---- register-prefetch main loop ----
    ldg_chunk(0);
    for (int kt = 0; kt < NCH; ++kt) {
        sts_chunk(kt & 1);                 // regs -> smem (cheap, exposed)
        __syncthreads();
        if (kt + 1 < NCH) ldg_chunk(kt + 1);   // long-latency, hidden below
        compute(sb0 + (unsigned)(kt & 1) * 24576u);
    }

    // ---- epilogue ----
#pragma unroll
    for (int mt = 0; mt < 4; ++mt) {
#pragma unroll
        for (int nt = 0; nt < 8; ++nt) {
            int row0 = m0 + wm + mt * 16 + (lane >> 2);
            int cc   = n0 + wn + nt * 8 + 2 * (lane & 3);
#pragma unroll
            for (int hrow = 0; hrow < 2; ++hrow) {
                float v0 = acc[mt][nt][2 * hrow + 0];
                float v1 = acc[mt][nt][2 * hrow + 1];
                if (FIRST) {
                    size_t g0 = ((size_t)e * K_CAP + row0 + 8 * hrow) * (size_t)F_DIM + cc;
                    float2 s;
                    s.x = silu_f(v0);
                    s.y = silu_f(v1);
                    *(float2*)(g_h + g0) = s;
                } else {
                    size_t g0 = kh * EOP
                              + ((size_t)e * K_CAP + row0 + 8 * hrow) * (size_t)H_DIM + cc;
                    float2 s;
                    s.x = v0;
                    s.y = v1;
                    *(float2*)(g_eo + g0) = s;
                }
            }
        }
    }
}

// ---------------- deterministic scatter (sums both split-K planes) ----------
__global__ void scatter_kernel(float* __restrict__ out) {
    int t = blockIdx.x, tid = threadIdx.x;
    __shared__ int ssl[E_NUM];
    if (tid < E_NUM) ssl[tid] = g_slot[t * E_NUM + tid];
    __syncthreads();
    int j = tid * 4;
    float4 sum = make_float4(0.f, 0.f, 0.f, 0.f);
#pragma unroll
    for (int e = 0; e < E_NUM; ++e) {
        int sl = ssl[e];
        if (sl >= 0) {
            size_t base = ((size_t)e * K_CAP + sl) * H_DIM + j;
            float4 v0 = *(const float4*)(g_eo + base);
            float4 v1 = *(const float4*)(g_eo + EOP + base);
            sum.x += v0.x + v1.x; sum.y += v0.y + v1.y;
            sum.z += v0.z + v1.z; sum.w += v0.w + v1.w;
        }
    }
    *(float4*)(out + (size_t)t * H_DIM + j) = sum;
}

// ---------------- launch ----------------------------------------------------
extern "C" void kernel_launch(void* const* d_in, const int* in_sizes, int n_in,
                              void* d_out, int out_size) {
    const float* x  = (const float*)d_in[0];   // [4,2048,1024]
    const float* gw = (const float*)d_in[1];   // [1024,8]
    const float* w1 = (const float*)d_in[2];   // [8,1024,4096]
    const float* w2 = (const float*)d_in[3];   // [8,4096,1024]
    float* out = (float*)d_out;
    (void)in_sizes; (void)n_in;

    // loss scalar = 0 exactly (expert_load == k for all experts)
    cudaMemsetAsync(d_out, 0, (size_t)out_size * sizeof(float), 0);

    gate_kernel<<<N_TOK, 256>>>(x, gw);
    sort_half_kernel<<<dim3(2, E_NUM), 1024>>>();
    merge_topk_kernel<<<E_NUM, 256>>>();

    moe_gemm_kernel<true, 1><<<dim3(F_DIM / 128, K_CAP / 128, E_NUM), 128>>>(x, w1);
    moe_gemm_kernel<false, 2><<<dim3(H_DIM / 128, K_CAP / 128, E_NUM * 2), 128>>>(nullptr, w2);

    scatter_kernel<<<N_TOK, 256>>>(out);
}